// round 10
// baseline (speedup 1.0000x reference)
#include <cuda_runtime.h>

#define DFEAT 128
#define MAXM 100000

// ---- persistent device scratch (allocation-free rule: __device__ globals) ----
__device__ float g_scratch[MAXM * DFEAT];   // 51.2 MB intermediate
__device__ float g_sum[DFEAT];
__device__ float g_sq[DFEAT];
__device__ float g_scale[DFEAT];
__device__ float g_shift[DFEAT];
__device__ int   g_idx_is64;

__device__ __forceinline__ unsigned f2tf32(float f) {
    unsigned u;
    asm("cvt.rna.tf32.f32 %0, %1;" : "=r"(u) : "f"(f));
    return u;
}

#define MMA_TF32_S(d, a0, a1, a2, a3, b0, b1) \
    asm volatile("mma.sync.aligned.m16n8k8.row.col.f32.tf32.tf32.f32 " \
        "{%0,%1,%2,%3}, {%4,%5,%6,%7}, {%8,%9}, {%0,%1,%2,%3};" \
        : "+f"((d)[0]), "+f"((d)[1]), "+f"((d)[2]), "+f"((d)[3]) \
        : "r"(a0), "r"(a1), "r"(a2), "r"(a3), "r"(b0), "r"(b1))

// ============================================================================
// K0: detect edge-index dtype (int32 vs int64) — parallel.
// ============================================================================
__global__ void detect_kernel(const long long* __restrict__ ei, int E, int Nnodes)
{
    int t = threadIdx.x;            // 64 threads
    int n = 2 * E < 64 ? 2 * E : 64;
    bool ok = true;
    if (t < n) {
        long long v = ei[t];
        ok = (v >= 0) && (v < (long long)Nnodes);
    }
    unsigned m0 = __ballot_sync(0xffffffffu, ok);
    __shared__ unsigned w[2];
    w[t >> 5] = m0;
    __syncthreads();
    if (t == 0) g_idx_is64 = (w[0] == 0xffffffffu && w[1] == 0xffffffffu) ? 1 : 0;
}

// ============================================================================
// K1: out = (1+eps) * x   (and reset BN stat accumulators)
// ============================================================================
__global__ void init_kernel(const float4* __restrict__ x,
                            float4* __restrict__ out,
                            const float* __restrict__ eps,
                            long total4)
{
    if (blockIdx.x == 0 && threadIdx.x < DFEAT) {
        g_sum[threadIdx.x] = 0.f;
        g_sq[threadIdx.x]  = 0.f;
    }
    float c = 1.0f + *eps;
    long i = (long)blockIdx.x * blockDim.x + threadIdx.x;
    long stride = (long)gridDim.x * blockDim.x;
    for (; i < total4; i += stride) {
        float4 v = x[i];
        v.x *= c; v.y *= c; v.z *= c; v.w *= c;
        out[i] = v;
    }
}

// ============================================================================
// K2: scatter-add  out[dst] += x[src]   (warp per edge, float4 vector atomics)
// ============================================================================
__global__ void scatter_kernel(const float4* __restrict__ x,
                               const void* __restrict__ ei_raw,
                               float4* __restrict__ out,
                               int E, int Nnodes)
{
    int e = blockIdx.x * 8 + (threadIdx.x >> 5);
    if (e >= E) return;
    int lane = threadIdx.x & 31;

    unsigned long long s, d;
    if (g_idx_is64) {
        const long long* ei = (const long long*)ei_raw;
        s = (unsigned long long)ei[e];
        d = (unsigned long long)ei[E + e];
    } else {
        const int* ei = (const int*)ei_raw;
        s = (unsigned long long)(unsigned)ei[e];
        d = (unsigned long long)(unsigned)ei[E + e];
    }
    if (s >= (unsigned long long)Nnodes || d >= (unsigned long long)Nnodes) return;
    float4 v = x[s * 32 + lane];
    atomicAdd(&out[d * 32 + lane], v);   // sm_90+ vector red
}

// ============================================================================
// K3/K5: SYNC-FREE persistent OUT-OF-PLACE GEMM (mma.sync tf32).
//   Cout[M,128] = f(Ain) @ W + bias ; Ain and Cout are DISJOINT buffers,
//   so warps are fully independent -> no barriers in the main loop.
//   - B (W) in smem only: row-permuted + col-bitswapped + XOR-swizzled.
//   - A fragments via direct LDG.128: lane (q,rg) loads (row, k16+4q..+3);
//     mma step s of a 16-wide k-block uses components {s, s+2}.
//   - warp tile 32 rows x 64 cols; warps wn=0/1 split N; persistent chunks.
//   - PHASE 1: BN sum/sumsq shuffle-reduced + global RED per chunk.
//   - PHASE 2: ReLU(BN(.)) applied to A fragments in registers.
// ============================================================================
template <int PHASE>
__global__ __launch_bounds__(256, 2)
void gemm_tc_kernel(const float* __restrict__ Ain,
                    float* __restrict__ Cout,
                    const float* __restrict__ W,
                    const float* __restrict__ bias,
                    int M, int nchunks)
{
    extern __shared__ unsigned Bs[];      // [128][128] words, swizzled
    __shared__ float s_scale[DFEAT];
    __shared__ float s_shift[DFEAT];
    __shared__ float s_bias[DFEAT];

    const int t    = threadIdx.x;
    const int lane = t & 31;
    const int warp = t >> 5;
    const int q    = lane & 3;
    const int rg   = lane >> 2;
    const int wn   = warp & 1;
    const int pair = warp >> 1;

    if (t < DFEAT) {
        s_bias[t] = bias[t];
        if (PHASE == 2) { s_scale[t] = g_scale[t]; s_shift[t] = g_shift[t]; }
    }

    // ---- B load (once): row-permute + col-bitswap + XOR swizzle ----
    // row permute: phys k = k0 + 4a + 2hi + s  ->  smem row k0 + 8s + 4hi + a
    // col bitswap: logical n -> col' = (n&64) | ((n&7)<<3) | ((n>>3)&7)
    // swizzle: physical quad pq = (col'>>2) ^ g(row), g = (r&1)|(((r>>1)&1)<<2)
#pragma unroll
    for (int i = 0; i < 16; i++) {
        int k  = i * 8 + warp;
        int j  = k & 15;
        int nk = (k & ~15) | ((j & 1) << 3) | (((j >> 1) & 1) << 2) | (j >> 2);
        unsigned gs = (unsigned)((nk & 1) | (((nk >> 1) & 1) << 2));
        unsigned pq = (unsigned)lane ^ gs;
        const float* Wr = W + (long)k * DFEAT;
        unsigned u[4];
#pragma unroll
        for (int jj = 0; jj < 4; jj++) {
            int cp = lane * 4 + jj;                      // col'
            int n  = (cp & 64) | ((cp & 7) << 3) | ((cp >> 3) & 7);
            u[jj]  = f2tf32(Wr[n]);
        }
        *reinterpret_cast<uint4*>(Bs + nk * DFEAT + pq * 4) =
            make_uint4(u[0], u[1], u[2], u[3]);
    }
    __syncthreads();   // the ONLY barrier

    const unsigned gq     = (unsigned)((q & 1) | (((q >> 1) & 1) << 2));
    const int      lqb    = wn * 16 + rg * 2;
    const unsigned off_a  = ((unsigned)lqb ^ gq) << 2;
    const unsigned off_b  = ((unsigned)(lqb + 1) ^ gq) << 2;

    for (int chunk = blockIdx.x * 4 + pair; chunk < nchunks;
         chunk += gridDim.x * 4) {
        const int rbase = chunk * 32;

        float acc[2][8][4];
#pragma unroll
        for (int mt = 0; mt < 2; mt++)
#pragma unroll
            for (int nt = 0; nt < 8; nt++)
#pragma unroll
                for (int jj = 0; jj < 4; jj++) acc[mt][nt][jj] = 0.f;

#pragma unroll
        for (int k16 = 0; k16 < DFEAT; k16 += 16) {
            // ---- A fragments: 4 x LDG.128 (mt x row-half) ----
            float4 a[4];
#pragma unroll
            for (int mt = 0; mt < 2; mt++)
#pragma unroll
                for (int h = 0; h < 2; h++) {
                    int r = rbase + mt * 16 + h * 8 + rg;
                    a[mt * 2 + h] = (r < M)
                        ? *reinterpret_cast<const float4*>(
                              Ain + (long)r * DFEAT + k16 + 4 * q)
                        : make_float4(0.f, 0.f, 0.f, 0.f);
                }
            if (PHASE == 2) {
                float4 sc = *reinterpret_cast<const float4*>(s_scale + k16 + 4 * q);
                float4 sh = *reinterpret_cast<const float4*>(s_shift + k16 + 4 * q);
#pragma unroll
                for (int ii = 0; ii < 4; ii++) {
                    a[ii].x = fmaxf(fmaf(a[ii].x, sc.x, sh.x), 0.f);
                    a[ii].y = fmaxf(fmaf(a[ii].y, sc.y, sh.y), 0.f);
                    a[ii].z = fmaxf(fmaf(a[ii].z, sc.z, sh.z), 0.f);
                    a[ii].w = fmaxf(fmaf(a[ii].w, sc.w, sh.w), 0.f);
                }
            }
            unsigned au[4][4];
#pragma unroll
            for (int ii = 0; ii < 4; ii++) {
                au[ii][0] = f2tf32(a[ii].x);
                au[ii][1] = f2tf32(a[ii].y);
                au[ii][2] = f2tf32(a[ii].z);
                au[ii][3] = f2tf32(a[ii].w);
            }
            // ---- two mma k-steps per k16 block ----
#pragma unroll
            for (int s = 0; s < 2; s++) {
                const unsigned* B0 = Bs + (k16 + s * 8 + q) * DFEAT;
                const unsigned* B1 = B0 + 4 * DFEAT;
                uint4 b0a = *reinterpret_cast<const uint4*>(B0 + off_a);
                uint4 b0b = *reinterpret_cast<const uint4*>(B0 + off_b);
                uint4 b1a = *reinterpret_cast<const uint4*>(B1 + off_a);
                uint4 b1b = *reinterpret_cast<const uint4*>(B1 + off_b);
                unsigned bb0[8] = {b0a.x, b0a.y, b0a.z, b0a.w,
                                   b0b.x, b0b.y, b0b.z, b0b.w};
                unsigned bb1[8] = {b1a.x, b1a.y, b1a.z, b1a.w,
                                   b1b.x, b1b.y, b1b.z, b1b.w};
#pragma unroll
                for (int mt = 0; mt < 2; mt++) {
                    unsigned a0 = au[mt * 2 + 0][s];
                    unsigned a1 = au[mt * 2 + 1][s];
                    unsigned a2 = au[mt * 2 + 0][s + 2];
                    unsigned a3 = au[mt * 2 + 1][s + 2];
#pragma unroll
                    for (int nt = 0; nt < 8; nt++)
                        MMA_TF32_S(acc[mt][nt], a0, a1, a2, a3,
                                   bb0[nt], bb1[nt]);
                }
            }
        }

        // ---- epilogue: bias, store, BN stats ----
        float csum[8][2], csq[8][2];
#pragma unroll
        for (int nt = 0; nt < 8; nt++) {
            csum[nt][0] = csum[nt][1] = 0.f;
            csq[nt][0]  = csq[nt][1]  = 0.f;
        }
#pragma unroll
        for (int mt = 0; mt < 2; mt++)
#pragma unroll
            for (int h = 0; h < 2; h++) {
                int row = rbase + mt * 16 + h * 8 + rg;
                if (row < M) {
#pragma unroll
                    for (int nt = 0; nt < 8; nt++) {
                        int col = wn * 64 + nt * 8 + 2 * q;
                        float2 bv = *reinterpret_cast<const float2*>(s_bias + col);
                        float v0 = acc[mt][nt][h * 2 + 0] + bv.x;
                        float v1 = acc[mt][nt][h * 2 + 1] + bv.y;
                        *reinterpret_cast<float2*>(Cout + (long)row * DFEAT + col) =
                            make_float2(v0, v1);
                        if (PHASE == 1) {
                            csum[nt][0] += v0; csq[nt][0] += v0 * v0;
                            csum[nt][1] += v1; csq[nt][1] += v1 * v1;
                        }
                    }
                }
            }

        if (PHASE == 1) {
#pragma unroll
            for (int nt = 0; nt < 8; nt++)
#pragma unroll
                for (int jj = 0; jj < 2; jj++) {
#pragma unroll
                    for (int ofs = 4; ofs < 32; ofs <<= 1) {
                        csum[nt][jj] += __shfl_xor_sync(0xffffffffu, csum[nt][jj], ofs);
                        csq[nt][jj]  += __shfl_xor_sync(0xffffffffu, csq[nt][jj],  ofs);
                    }
                }
            if (rg == 0) {
#pragma unroll
                for (int nt = 0; nt < 8; nt++) {
                    int col = wn * 64 + nt * 8 + 2 * q;
                    atomicAdd(&g_sum[col],     csum[nt][0]);
                    atomicAdd(&g_sum[col + 1], csum[nt][1]);
                    atomicAdd(&g_sq[col],      csq[nt][0]);
                    atomicAdd(&g_sq[col + 1],  csq[nt][1]);
                }
            }
        }
    }
}

// ============================================================================
// K4: fold BN stats into affine scale/shift
// ============================================================================
__global__ void finalize_kernel(const float* __restrict__ gamma,
                                const float* __restrict__ beta,
                                float invM)
{
    int t = threadIdx.x;
    float mu   = g_sum[t] * invM;
    float var  = g_sq[t] * invM - mu * mu;
    float rstd = rsqrtf(var + 1e-5f);
    float sc   = rstd * gamma[t];
    g_scale[t] = sc;
    g_shift[t] = beta[t] - mu * sc;
}

// ============================================================================
// launch: resolve inputs by size signature (robust to metadata ordering)
// ============================================================================
extern "C" void kernel_launch(void* const* d_in, const int* in_sizes, int n_in,
                              void* d_out, int out_size)
{
    int ix = -1, ie = -1, iW1 = -1, iW2 = -1, ieps = -1;
    int v128[8]; int n128 = 0;
    long best_x = -1, best_e = -1;
    for (int i = 0; i < n_in; i++) {
        long sz = in_sizes[i];
        if (sz > best_x) {
            best_e = best_x; ie = ix;
            best_x = sz; ix = i;
        } else if (sz > best_e) { best_e = sz; ie = i; }
    }
    for (int i = 0; i < n_in; i++) {
        if (i == ix || i == ie) continue;
        long sz = in_sizes[i];
        if (sz == DFEAT * DFEAT) { if (iW1 < 0) iW1 = i; else iW2 = i; }
        else if (sz == DFEAT)    { if (n128 < 8) v128[n128++] = i; }
        else                     { ieps = i; }
    }
    int ib1, igamma, ibeta, ib2;
    if (ix == 0) { ib1 = v128[0]; igamma = v128[1]; ibeta = v128[2]; ib2 = v128[3]; }
    else         { ib1 = v128[0]; ib2 = v128[1];    ibeta = v128[2]; igamma = v128[3]; }

    const float* x     = (const float*)d_in[ix];
    const void*  ei    = d_in[ie];
    const float* W1    = (const float*)d_in[iW1];
    const float* b1    = (const float*)d_in[ib1];
    const float* gamma = (const float*)d_in[igamma];
    const float* beta  = (const float*)d_in[ibeta];
    const float* W2    = (const float*)d_in[iW2];
    const float* b2    = (const float*)d_in[ib2];
    const float* eps   = (const float*)d_in[ieps];
    float*       out   = (float*)d_out;

    int M = in_sizes[ix] / DFEAT;
    int E = in_sizes[ie] / 2;
    long total4 = (long)M * (DFEAT / 4);

    // resolve scratch device-global address (host-side, capture-safe)
    static float* scratch = nullptr;
    static int nsm = 0;
    const int dyn_smem = DFEAT * DFEAT * 4;   // 65536 B (B tile only)
    if (!nsm) {
        cudaGetSymbolAddress((void**)&scratch, g_scratch);
        cudaFuncSetAttribute(gemm_tc_kernel<1>,
                             cudaFuncAttributeMaxDynamicSharedMemorySize, dyn_smem);
        cudaFuncSetAttribute(gemm_tc_kernel<2>,
                             cudaFuncAttributeMaxDynamicSharedMemorySize, dyn_smem);
        cudaDeviceGetAttribute(&nsm, cudaDevAttrMultiProcessorCount, 0);
        if (nsm <= 0) nsm = 148;
    }

    // K0: detect edge-index dtype (parallel)
    detect_kernel<<<1, 64>>>((const long long*)ei, E, M);

    // K1: out = (1+eps)*x ; zero stat accumulators
    init_kernel<<<2048, 256>>>((const float4*)x, (float4*)out, eps, total4);

    // K2: out[dst] += x[src]  (GIN sum aggregation)
    scatter_kernel<<<(E + 7) / 8, 256>>>((const float4*)x, ei, (float4*)out, E, M);

    int nchunks = (M + 31) / 32;
    int pgrid   = 2 * nsm;
    int maxg    = (nchunks + 3) / 4;
    if (pgrid > maxg) pgrid = maxg;

    // K3: scratch = out @ W1 + b1 (out-of-place), BN stats accumulated
    gemm_tc_kernel<1><<<pgrid, 256, dyn_smem>>>(out, scratch, W1, b1, M, nchunks);

    // K4: fold mean/var/gamma/beta into scale/shift
    finalize_kernel<<<1, DFEAT>>>(gamma, beta, 1.0f / (float)M);

    // K5: out = ReLU(BN(scratch)) @ W2 + b2 (out-of-place)
    gemm_tc_kernel<2><<<pgrid, 256, dyn_smem>>>(scratch, out, W2, b2, M, nchunks);
}

// round 11
// speedup vs baseline: 1.8235x; 1.8235x over previous
#include <cuda_runtime.h>

#define DFEAT 128
#define BM 64
#define SA 136
#define SB 136
#define MAXN 100000
#define MAXE 655360

// ---- persistent device scratch (allocation-free rule: __device__ globals) ----
__device__ int   g_cnt[MAXN];
__device__ int   g_col[MAXN * 32];
__device__ int   g_ovf[2 * MAXE];
__device__ int   g_ovf_n;
__device__ float g_sum[DFEAT];
__device__ float g_sq[DFEAT];
__device__ float g_scale[DFEAT];
__device__ float g_shift[DFEAT];
__device__ int   g_idx_is64;

__device__ __forceinline__ unsigned f2tf32(float f) {
    unsigned u;
    asm("cvt.rna.tf32.f32 %0, %1;" : "=r"(u) : "f"(f));
    return u;
}

#define MMA_TF32_S(d, a0, a1, a2, a3, b0, b1) \
    asm volatile("mma.sync.aligned.m16n8k8.row.col.f32.tf32.tf32.f32 " \
        "{%0,%1,%2,%3}, {%4,%5,%6,%7}, {%8,%9}, {%0,%1,%2,%3};" \
        : "+f"((d)[0]), "+f"((d)[1]), "+f"((d)[2]), "+f"((d)[3]) \
        : "r"(a0), "r"(a1), "r"(a2), "r"(a3), "r"(b0), "r"(b1))

// ============================================================================
// K0: detect edge-index dtype (int32 vs int64) — parallel.
// ============================================================================
__global__ void detect_kernel(const long long* __restrict__ ei, int E, int Nnodes)
{
    int t = threadIdx.x;            // 64 threads
    int n = 2 * E < 64 ? 2 * E : 64;
    bool ok = true;
    if (t < n) {
        long long v = ei[t];
        ok = (v >= 0) && (v < (long long)Nnodes);
    }
    unsigned m0 = __ballot_sync(0xffffffffu, ok);
    __shared__ unsigned w[2];
    w[t >> 5] = m0;
    __syncthreads();
    if (t == 0) g_idx_is64 = (w[0] == 0xffffffffu && w[1] == 0xffffffffu) ? 1 : 0;
}

// ============================================================================
// K1: zero per-node counters, BN stat accumulators, overflow counter
// ============================================================================
__global__ void zero_kernel(int M)
{
    int i = blockIdx.x * blockDim.x + threadIdx.x;
    if (i < M) g_cnt[i] = 0;
    if (i < DFEAT) { g_sum[i] = 0.f; g_sq[i] = 0.f; }
    if (i == 0) g_ovf_n = 0;
}

// ============================================================================
// K2: build padded CSR — bucket src indices by dst (32 slots/node; overflow
// edges appended to a list handled by the atomic fallback kernel).
// ============================================================================
__global__ void fill_kernel(const void* __restrict__ ei_raw, int E, int M)
{
    int e = blockIdx.x * blockDim.x + threadIdx.x;
    if (e >= E) return;
    unsigned long long s, d;
    if (g_idx_is64) {
        const long long* ei = (const long long*)ei_raw;
        s = (unsigned long long)ei[e];
        d = (unsigned long long)ei[E + e];
    } else {
        const int* ei = (const int*)ei_raw;
        s = (unsigned long long)(unsigned)ei[e];
        d = (unsigned long long)(unsigned)ei[E + e];
    }
    if (s >= (unsigned long long)M || d >= (unsigned long long)M) return;
    int pos = atomicAdd(&g_cnt[(int)d], 1);
    if (pos < 32) {
        g_col[(int)d * 32 + pos] = (int)s;
    } else {
        int o = atomicAdd(&g_ovf_n, 1);
        if (o < MAXE) { g_ovf[2 * o] = (int)s; g_ovf[2 * o + 1] = (int)d; }
    }
}

// ============================================================================
// K3: gather-sum (replaces init + scatter):
//   out[node] = sum_{src in nbr(node)} x[src] + (1+eps) * x[node]
// Warp per node; lane = float4 column; neighbor idx broadcast via shfl.
// ============================================================================
__global__ void gather_kernel(const float4* __restrict__ x,
                              float4* __restrict__ out,
                              const float* __restrict__ eps,
                              int M)
{
    int node = blockIdx.x * 8 + (threadIdx.x >> 5);
    if (node >= M) return;
    int lane = threadIdx.x & 31;

    int cnt = g_cnt[node];
    if (cnt > 32) cnt = 32;
    int src = (lane < cnt) ? g_col[node * 32 + lane] : 0;

    float c = 1.0f + *eps;
    float4 acc = x[(long)node * 32 + lane];
    acc.x *= c; acc.y *= c; acc.z *= c; acc.w *= c;

    #pragma unroll 4
    for (int j = 0; j < cnt; j++) {
        int s = __shfl_sync(0xffffffffu, src, j);
        float4 v = x[(long)s * 32 + lane];
        acc.x += v.x; acc.y += v.y; acc.z += v.z; acc.w += v.w;
    }
    out[(long)node * 32 + lane] = acc;
}

// ============================================================================
// K4: overflow edges (deg>32) — atomic fallback; nearly always 0 edges.
// ============================================================================
__global__ void ovf_kernel(const float4* __restrict__ x,
                           float4* __restrict__ out)
{
    int n = g_ovf_n;
    if (n > MAXE) n = MAXE;
    int lane = threadIdx.x & 31;
    for (int i = blockIdx.x * 8 + (threadIdx.x >> 5); i < n; i += gridDim.x * 8) {
        int s = g_ovf[2 * i], d = g_ovf[2 * i + 1];
        atomicAdd(&out[(long)d * 32 + lane], x[(long)s * 32 + lane]);
    }
}

// ============================================================================
// K5/K7: PERSISTENT in-place GEMM via mma.sync tf32 (proven R8 kernel).
//   C[M,128] = f(C) @ W + bias
//   - B (W) loaded to smem ONCE per CTA (k-rows permuted).
//   - next tile's A prefetched into registers during current tile's MMA.
//   - PHASE 1: BN sum/sumsq accumulated in regs, flushed once per CTA.
//   - PHASE 2: ReLU(BN(.)) applied at A store-to-smem.
// ============================================================================
template <int PHASE>
__global__ __launch_bounds__(256, 2)
void gemm_tc_kernel(float* __restrict__ C,
                    const float* __restrict__ W,
                    const float* __restrict__ bias,
                    int M, int ntiles)
{
    extern __shared__ unsigned smem_u[];
    unsigned* As = smem_u;                // [64][SA]
    unsigned* Bs = smem_u + BM * SA;      // [128][SB] (k-rows permuted)
    __shared__ float s_scale[DFEAT];
    __shared__ float s_shift[DFEAT];

    const int t    = threadIdx.x;
    const int lane = t & 31;
    const int warp = t >> 5;

    int tile = blockIdx.x;
    float4 areg[8];
    if (tile < ntiles) {
#pragma unroll
        for (int i = 0; i < 8; i++) {
            int m = tile * BM + i * 8 + warp;
            areg[i] = (m < M)
                ? *reinterpret_cast<const float4*>(C + (long)m * DFEAT + lane * 4)
                : make_float4(0.f, 0.f, 0.f, 0.f);
        }
    }

    if (PHASE == 2) {
        if (t < DFEAT) { s_scale[t] = g_scale[t]; s_shift[t] = g_shift[t]; }
    }

#pragma unroll
    for (int i = 0; i < 16; i++) {
        int k  = i * 8 + warp;
        int nk = (k & ~7) | ((k & 1) << 2) | ((k & 7) >> 1);
        float4 v = *reinterpret_cast<const float4*>(W + (long)k * DFEAT + lane * 4);
        uint4 u = make_uint4(f2tf32(v.x), f2tf32(v.y), f2tf32(v.z), f2tf32(v.w));
        *reinterpret_cast<uint4*>(Bs + nk * SB + lane * 4) = u;
    }

    const int wm = warp >> 2;
    const int wn = warp & 3;
    const int q  = lane & 3;
    const int rg = lane >> 2;

    float bv[4][2];
#pragma unroll
    for (int nt = 0; nt < 4; nt++) {
        int col = wn * 32 + nt * 8 + 2 * q;
        bv[nt][0] = bias[col];
        bv[nt][1] = bias[col + 1];
    }

    float csum[4][2] = {{0.f,0.f},{0.f,0.f},{0.f,0.f},{0.f,0.f}};
    float csq [4][2] = {{0.f,0.f},{0.f,0.f},{0.f,0.f},{0.f,0.f}};

    const unsigned* Abase = As + (wm * 32 + rg) * SA + 2 * q;
    const unsigned* Bbase = Bs + q * SB + wn * 32 + rg;
    unsigned* Asts = As + warp * SA + lane * 4;

    __syncthreads();

    while (tile < ntiles) {
#pragma unroll
        for (int i = 0; i < 8; i++) {
            float4 v = areg[i];
            if (PHASE == 2) {
                int kb = lane * 4;
                v.x = fmaxf(fmaf(v.x, s_scale[kb + 0], s_shift[kb + 0]), 0.f);
                v.y = fmaxf(fmaf(v.y, s_scale[kb + 1], s_shift[kb + 1]), 0.f);
                v.z = fmaxf(fmaf(v.z, s_scale[kb + 2], s_shift[kb + 2]), 0.f);
                v.w = fmaxf(fmaf(v.w, s_scale[kb + 3], s_shift[kb + 3]), 0.f);
            }
            uint4 u = make_uint4(f2tf32(v.x), f2tf32(v.y), f2tf32(v.z), f2tf32(v.w));
            *reinterpret_cast<uint4*>(Asts + i * 8 * SA) = u;
        }
        __syncthreads();

        int next = tile + gridDim.x;
        if (next < ntiles) {
#pragma unroll
            for (int i = 0; i < 8; i++) {
                int m = next * BM + i * 8 + warp;
                areg[i] = (m < M)
                    ? *reinterpret_cast<const float4*>(C + (long)m * DFEAT + lane * 4)
                    : make_float4(0.f, 0.f, 0.f, 0.f);
            }
        }

        float acc[2][4][4];
#pragma unroll
        for (int mt = 0; mt < 2; mt++)
#pragma unroll
            for (int nt = 0; nt < 4; nt++)
#pragma unroll
                for (int j = 0; j < 4; j++) acc[mt][nt][j] = 0.f;

#pragma unroll
        for (int k0 = 0; k0 < DFEAT; k0 += 8) {
            uint2 alo[2], ahi[2];
#pragma unroll
            for (int mt = 0; mt < 2; mt++) {
                alo[mt] = *reinterpret_cast<const uint2*>(Abase + mt * 16 * SA + k0);
                ahi[mt] = *reinterpret_cast<const uint2*>(Abase + (mt * 16 + 8) * SA + k0);
            }
            unsigned b0[4], b1[4];
#pragma unroll
            for (int nt = 0; nt < 4; nt++) {
                b0[nt] = Bbase[k0 * SB + nt * 8];
                b1[nt] = Bbase[(k0 + 4) * SB + nt * 8];
            }
#pragma unroll
            for (int mt = 0; mt < 2; mt++)
#pragma unroll
                for (int nt = 0; nt < 4; nt++)
                    MMA_TF32_S(acc[mt][nt],
                               alo[mt].x, ahi[mt].x, alo[mt].y, ahi[mt].y,
                               b0[nt], b1[nt]);
        }
        __syncthreads();

        int mb = tile * BM;
#pragma unroll
        for (int mt = 0; mt < 2; mt++) {
            int r0 = mb + wm * 32 + mt * 16 + rg;
            int r1 = r0 + 8;
#pragma unroll
            for (int nt = 0; nt < 4; nt++) {
                int col = wn * 32 + nt * 8 + 2 * q;
                float v0 = acc[mt][nt][0] + bv[nt][0];
                float v1 = acc[mt][nt][1] + bv[nt][1];
                float v2 = acc[mt][nt][2] + bv[nt][0];
                float v3 = acc[mt][nt][3] + bv[nt][1];
                if (r0 < M) {
                    *reinterpret_cast<float2*>(C + (long)r0 * DFEAT + col) =
                        make_float2(v0, v1);
                    if (PHASE == 1) {
                        csum[nt][0] += v0; csq[nt][0] += v0 * v0;
                        csum[nt][1] += v1; csq[nt][1] += v1 * v1;
                    }
                }
                if (r1 < M) {
                    *reinterpret_cast<float2*>(C + (long)r1 * DFEAT + col) =
                        make_float2(v2, v3);
                    if (PHASE == 1) {
                        csum[nt][0] += v2; csq[nt][0] += v2 * v2;
                        csum[nt][1] += v3; csq[nt][1] += v3 * v3;
                    }
                }
            }
        }
        tile = next;
    }

    if (PHASE == 1) {
#pragma unroll
        for (int nt = 0; nt < 4; nt++)
#pragma unroll
            for (int j = 0; j < 2; j++) {
#pragma unroll
                for (int ofs = 4; ofs < 32; ofs <<= 1) {
                    csum[nt][j] += __shfl_xor_sync(0xffffffffu, csum[nt][j], ofs);
                    csq[nt][j]  += __shfl_xor_sync(0xffffffffu, csq[nt][j],  ofs);
                }
            }
        if (rg == 0) {
#pragma unroll
            for (int nt = 0; nt < 4; nt++) {
                int col = wn * 32 + nt * 8 + 2 * q;
                atomicAdd(&g_sum[col],     csum[nt][0]);
                atomicAdd(&g_sum[col + 1], csum[nt][1]);
                atomicAdd(&g_sq[col],      csq[nt][0]);
                atomicAdd(&g_sq[col + 1],  csq[nt][1]);
            }
        }
    }
}

// ============================================================================
// K6: fold BN stats into affine scale/shift
// ============================================================================
__global__ void finalize_kernel(const float* __restrict__ gamma,
                                const float* __restrict__ beta,
                                float invM)
{
    int t = threadIdx.x;
    float mu   = g_sum[t] * invM;
    float var  = g_sq[t] * invM - mu * mu;
    float rstd = rsqrtf(var + 1e-5f);
    float sc   = rstd * gamma[t];
    g_scale[t] = sc;
    g_shift[t] = beta[t] - mu * sc;
}

// ============================================================================
// launch: resolve inputs by size signature (robust to metadata ordering)
// ============================================================================
extern "C" void kernel_launch(void* const* d_in, const int* in_sizes, int n_in,
                              void* d_out, int out_size)
{
    int ix = -1, ie = -1, iW1 = -1, iW2 = -1, ieps = -1;
    int v128[8]; int n128 = 0;
    long best_x = -1, best_e = -1;
    for (int i = 0; i < n_in; i++) {
        long sz = in_sizes[i];
        if (sz > best_x) {
            best_e = best_x; ie = ix;
            best_x = sz; ix = i;
        } else if (sz > best_e) { best_e = sz; ie = i; }
    }
    for (int i = 0; i < n_in; i++) {
        if (i == ix || i == ie) continue;
        long sz = in_sizes[i];
        if (sz == DFEAT * DFEAT) { if (iW1 < 0) iW1 = i; else iW2 = i; }
        else if (sz == DFEAT)    { if (n128 < 8) v128[n128++] = i; }
        else                     { ieps = i; }
    }
    int ib1, igamma, ibeta, ib2;
    if (ix == 0) { ib1 = v128[0]; igamma = v128[1]; ibeta = v128[2]; ib2 = v128[3]; }
    else         { ib1 = v128[0]; ib2 = v128[1];    ibeta = v128[2]; igamma = v128[3]; }

    const float* x     = (const float*)d_in[ix];
    const void*  ei    = d_in[ie];
    const float* W1    = (const float*)d_in[iW1];
    const float* b1    = (const float*)d_in[ib1];
    const float* gamma = (const float*)d_in[igamma];
    const float* beta  = (const float*)d_in[ibeta];
    const float* W2    = (const float*)d_in[iW2];
    const float* b2    = (const float*)d_in[ib2];
    const float* eps   = (const float*)d_in[ieps];
    float*       out   = (float*)d_out;

    int M = in_sizes[ix] / DFEAT;
    int E = in_sizes[ie] / 2;
    if (M > MAXN) M = MAXN;   // static bucket capacity guard

    static int nsm = 0;
    const int dyn_smem = (BM * SA + 128 * SB) * 4;   // 104,448 B -> 2 CTA/SM
    if (!nsm) {
        cudaFuncSetAttribute(gemm_tc_kernel<1>,
                             cudaFuncAttributeMaxDynamicSharedMemorySize, dyn_smem);
        cudaFuncSetAttribute(gemm_tc_kernel<2>,
                             cudaFuncAttributeMaxDynamicSharedMemorySize, dyn_smem);
        cudaDeviceGetAttribute(&nsm, cudaDevAttrMultiProcessorCount, 0);
        if (nsm <= 0) nsm = 148;
    }

    // K0: detect edge-index dtype
    detect_kernel<<<1, 64>>>((const long long*)ei, E, M);

    // K1: zero counters + BN stats
    zero_kernel<<<(M + 255) / 256, 256>>>(M);

    // K2: bucket edges by dst (padded CSR)
    fill_kernel<<<(E + 255) / 256, 256>>>(ei, E, M);

    // K3: out[n] = sum_nbr x[src] + (1+eps) x[n]   (fuses init + aggregation)
    gather_kernel<<<(M + 7) / 8, 256>>>((const float4*)x, (float4*)out, eps, M);

    // K4: rare deg>32 overflow edges via atomics
    ovf_kernel<<<64, 256>>>((const float4*)x, (float4*)out);

    int ntiles = (M + BM - 1) / BM;
    int pgrid  = 2 * nsm;
    if (pgrid > ntiles) pgrid = ntiles;

    // K5: out = out @ W1 + b1 (in place, persistent), BN stats accumulated
    gemm_tc_kernel<1><<<pgrid, 256, dyn_smem>>>(out, W1, b1, M, ntiles);

    // K6: fold mean/var/gamma/beta into scale/shift
    finalize_kernel<<<1, DFEAT>>>(gamma, beta, 1.0f / (float)M);

    // K7: out = ReLU(BN(out)) @ W2 + b2 (in place, persistent)
    gemm_tc_kernel<2><<<pgrid, 256, dyn_smem>>>(out, W2, b2, M, ntiles);
}